// round 2
// baseline (speedup 1.0000x reference)
#include <cuda_runtime.h>
#include <cuda_bf16.h>
#include <math.h>

#define NN 100000
#define NE 1600000
#define DD 128
#define NG 64
#define JK (3*DD)   // 384

// ---------------- scratch (device globals: allocation-free) ----------------
__device__ float g_dinv[NN];                 // deg -> dinv (in place)
__device__ float g_norm[NE];                 // per-edge symmetric norm
__device__ float g_bufA[(size_t)NN*DD];      // GEMM output h = X@W
__device__ float g_bufB[(size_t)NN*DD];      // segment-sum accumulator / layer output
__device__ float g_pooled[NG*JK];            // graph-pooled JK features
__device__ float g_cnt[NG];                  // nodes per graph
__device__ float g_dense[NG*DD];             // hidden of head MLP

// ---------------- graph preprocessing ----------------
__global__ void k_init() {
    int i = blockIdx.x*256 + threadIdx.x;
    if (i < NN) g_dinv[i] = 1.0f;            // self-loop contributes 1 to degree
    if (i < NG*JK) g_pooled[i] = 0.0f;
    if (i < NG) g_cnt[i] = 0.0f;
}

__global__ void k_deg(const int* __restrict__ ei) {
    int e = blockIdx.x*256 + threadIdx.x;
    if (e < NE) atomicAdd(&g_dinv[ei[NE + e]], 1.0f);
}

__global__ void k_dinv_cnt(const int* __restrict__ batch) {
    int i = blockIdx.x*256 + threadIdx.x;
    if (i < NN) {
        g_dinv[i] = rsqrtf(g_dinv[i]);       // deg >= 1 always (self loop)
        atomicAdd(&g_cnt[batch[i]], 1.0f);
    }
}

__global__ void k_norm(const int* __restrict__ ei) {
    int e = blockIdx.x*256 + threadIdx.x;
    if (e < NE) g_norm[e] = g_dinv[ei[e]] * g_dinv[ei[NE + e]];
}

// ---------------- dense GEMM: out(g_bufA) = X @ W, X: [NN,128], W: [128,128] ----------------
__global__ __launch_bounds__(256, 2) void k_gemm(const float* __restrict__ Xext,
                                                 const float* __restrict__ W,
                                                 int use_ext) {
    const float* X = use_ext ? Xext : g_bufB;
    extern __shared__ float sh[];
    float* Ws = sh;             // 128*128 floats = 64 KB
    float* Xs = sh + 128*128;   // 64*128 floats = 32 KB

    int t = threadIdx.x;
    int row0 = blockIdx.x * 64;

    // load W (full 128x128)
    for (int i = t; i < 128*128/4; i += 256)
        ((float4*)Ws)[i] = ((const float4*)W)[i];
    // load X tile (64 rows)
    for (int i = t; i < 64*128/4; i += 256) {
        int r = i >> 5;                 // 32 float4 per row
        int row = row0 + r;
        float4 v = make_float4(0.f,0.f,0.f,0.f);
        if (row < NN) v = ((const float4*)(X + (size_t)row*DD))[i & 31];
        ((float4*)Xs)[i] = v;
    }
    __syncthreads();

    int c0 = (t & 15) * 8;
    int r0 = (t >> 4) * 4;

    float4 acc[4][2];
    #pragma unroll
    for (int i = 0; i < 4; i++) {
        acc[i][0] = make_float4(0.f,0.f,0.f,0.f);
        acc[i][1] = make_float4(0.f,0.f,0.f,0.f);
    }

    for (int k = 0; k < 128; k += 4) {
        float4 xr[4];
        #pragma unroll
        for (int i = 0; i < 4; i++)
            xr[i] = *(float4*)(Xs + (r0 + i)*128 + k);
        #pragma unroll
        for (int kk = 0; kk < 4; kk++) {
            float4 w0 = *(float4*)(Ws + (k + kk)*128 + c0);
            float4 w1 = *(float4*)(Ws + (k + kk)*128 + c0 + 4);
            #pragma unroll
            for (int i = 0; i < 4; i++) {
                float xv = (kk==0) ? xr[i].x : (kk==1) ? xr[i].y : (kk==2) ? xr[i].z : xr[i].w;
                acc[i][0].x = fmaf(xv, w0.x, acc[i][0].x);
                acc[i][0].y = fmaf(xv, w0.y, acc[i][0].y);
                acc[i][0].z = fmaf(xv, w0.z, acc[i][0].z);
                acc[i][0].w = fmaf(xv, w0.w, acc[i][0].w);
                acc[i][1].x = fmaf(xv, w1.x, acc[i][1].x);
                acc[i][1].y = fmaf(xv, w1.y, acc[i][1].y);
                acc[i][1].z = fmaf(xv, w1.z, acc[i][1].z);
                acc[i][1].w = fmaf(xv, w1.w, acc[i][1].w);
            }
        }
    }

    #pragma unroll
    for (int i = 0; i < 4; i++) {
        int row = row0 + r0 + i;
        if (row < NN) {
            *(float4*)(g_bufA + (size_t)row*DD + c0)     = acc[i][0];
            *(float4*)(g_bufA + (size_t)row*DD + c0 + 4) = acc[i][1];
        }
    }
}

// ---------------- zero the accumulator ----------------
__global__ void k_zeroB() {
    int i = blockIdx.x*256 + threadIdx.x;   // NN*DD/4 = 3.2M float4
    ((float4*)g_bufB)[i] = make_float4(0.f,0.f,0.f,0.f);
}

// ---------------- edge scatter: bufB[dst] += norm * bufA[src] ----------------
__global__ __launch_bounds__(256) void k_scatter(const int* __restrict__ ei) {
    int e = blockIdx.x*8 + (threadIdx.x >> 5);
    if (e >= NE) return;
    int lane = threadIdx.x & 31;
    int s = __ldg(&ei[e]);
    int d = __ldg(&ei[NE + e]);
    float nm = __ldg(&g_norm[e]);
    float4 v = *(const float4*)(g_bufA + (size_t)s*DD + lane*4);
    v.x *= nm; v.y *= nm; v.z *= nm; v.w *= nm;
    float* q = g_bufB + (size_t)d*DD + lane*4;
    asm volatile("red.global.add.v4.f32 [%0], {%1,%2,%3,%4};"
                 :: "l"(q), "f"(v.x), "f"(v.y), "f"(v.z), "f"(v.w) : "memory");
}

// ---------------- self-loop + bias + relu + block-aggregated pooling ----------------
__global__ __launch_bounds__(128) void k_finish(const float* __restrict__ b,
                                                const int* __restrict__ batch,
                                                int off) {
    int c = threadIdx.x;                    // 128 cols
    int n0 = blockIdx.x * 64;
    if (n0 >= NN) return;
    float bc = b[c];
    int cur = batch[n0];
    float accv = 0.f;
    for (int r = 0; r < 64; r++) {
        int n = n0 + r;
        if (n >= NN) break;
        float di = g_dinv[n];
        size_t idx = (size_t)n*DD + c;
        float v = g_bufB[idx] + di*di*g_bufA[idx] + bc;
        v = fmaxf(v, 0.f);
        g_bufB[idx] = v;
        int g = batch[n];                   // uniform across block
        if (g != cur) {
            atomicAdd(&g_pooled[cur*JK + off + c], accv);
            accv = 0.f; cur = g;
        }
        accv += v;
    }
    atomicAdd(&g_pooled[cur*JK + off + c], accv);
}

// ---------------- head: mean-pool normalize + lin1 + relu ----------------
__global__ __launch_bounds__(128) void k_head1(const float* __restrict__ l1w,
                                               const float* __restrict__ l1b) {
    int g = blockIdx.x;                     // 64 graphs
    int j = threadIdx.x;                    // 128 out cols
    __shared__ float ps[JK];
    float inv = 1.f / fmaxf(g_cnt[g], 1.f);
    for (int k = j; k < JK; k += 128) ps[k] = g_pooled[g*JK + k] * inv;
    __syncthreads();
    float s = l1b[j];
    #pragma unroll 4
    for (int k = 0; k < JK; k++) s = fmaf(ps[k], l1w[k*DD + j], s);
    g_dense[g*DD + j] = fmaxf(s, 0.f);
}

// ---------------- head: lin2 + log_softmax ----------------
__global__ __launch_bounds__(64) void k_head2(const float* __restrict__ l2w,
                                              const float* __restrict__ l2b,
                                              float* __restrict__ out) {
    __shared__ float ws[DD*10];
    __shared__ float bs[10];
    int t = threadIdx.x;                    // 64
    for (int i = t; i < DD*10; i += 64) ws[i] = l2w[i];
    if (t < 10) bs[t] = l2b[t];
    __syncthreads();
    if (t < NG) {
        float z[10];
        #pragma unroll
        for (int c = 0; c < 10; c++) z[c] = bs[c];
        for (int k = 0; k < DD; k++) {
            float gv = g_dense[t*DD + k];
            #pragma unroll
            for (int c = 0; c < 10; c++) z[c] = fmaf(gv, ws[k*10 + c], z[c]);
        }
        float m = z[0];
        #pragma unroll
        for (int c = 1; c < 10; c++) m = fmaxf(m, z[c]);
        float ssum = 0.f;
        #pragma unroll
        for (int c = 0; c < 10; c++) ssum += expf(z[c] - m);
        float ls = m + logf(ssum);
        #pragma unroll
        for (int c = 0; c < 10; c++) out[t*10 + c] = z[c] - ls;
    }
}

// ---------------- launch ----------------
extern "C" void kernel_launch(void* const* d_in, const int* in_sizes, int n_in,
                              void* d_out, int out_size) {
    const float* x     = (const float*)d_in[0];
    const int*   ei    = (const int*)  d_in[1];   // [2, NE] int32
    const int*   batch = (const int*)  d_in[2];
    // d_in[3] = target_size (64), fixed
    const float* W1 = (const float*)d_in[4];  const float* b1 = (const float*)d_in[5];
    const float* W2 = (const float*)d_in[6];  const float* b2 = (const float*)d_in[7];
    const float* W3 = (const float*)d_in[8];  const float* b3 = (const float*)d_in[9];
    const float* l1w = (const float*)d_in[10]; const float* l1b = (const float*)d_in[11];
    const float* l2w = (const float*)d_in[12]; const float* l2b = (const float*)d_in[13];
    float* out = (float*)d_out;

    cudaFuncSetAttribute(k_gemm, cudaFuncAttributeMaxDynamicSharedMemorySize, 98304);

    k_init    <<<(NN + 255)/256, 256>>>();
    k_deg     <<<(NE + 255)/256, 256>>>(ei);
    k_dinv_cnt<<<(NN + 255)/256, 256>>>(batch);
    k_norm    <<<(NE + 255)/256, 256>>>(ei);

    const float* Wl[3] = {W1, W2, W3};
    const float* bl[3] = {b1, b2, b3};
    for (int l = 0; l < 3; l++) {
        k_gemm   <<<(NN + 63)/64, 256, 98304>>>(x, Wl[l], l == 0 ? 1 : 0);
        k_zeroB  <<<(NN*DD/4 + 255)/256, 256>>>();
        k_scatter<<<(NE + 7)/8, 256>>>(ei);
        k_finish <<<(NN + 63)/64, 128>>>(bl[l], batch, l*DD);
    }

    k_head1<<<NG, 128>>>(l1w, l1b);
    k_head2<<<1, 64>>>(l2w, l2b, out);
}

// round 3
// speedup vs baseline: 1.7211x; 1.7211x over previous
#include <cuda_runtime.h>
#include <cuda_bf16.h>
#include <math.h>

#define NN 100000
#define NE 1600000
#define DD 128
#define NG 64
#define JK (3*DD)   // 384

#define NB_SCAN 98          // ceil(NN/1024)
#define XS_STRIDE 132       // padded smem row (conflict-free A frags)
#define WS_STRIDE 136       // padded smem row (conflict-free B frags)

// ---------------- scratch (device globals: allocation-free) ----------------
__device__ float  g_dinv[NN];
__device__ int    g_deg[NN];
__device__ int    g_inc[NN];            // block-local inclusive scan
__device__ int    g_part[NB_SCAN];
__device__ int    g_off[NN + 1];        // CSR offsets (by dst)
__device__ int    g_fill[NN];           // bucket fill cursors
__device__ float2 g_meta[NE];           // {src_as_float_bits, norm} dst-sorted
__device__ float  g_bufA[(size_t)NN*DD]; // GEMM output h = X@W
__device__ float  g_bufB[(size_t)NN*DD]; // layer output (post aggregate+relu)
__device__ float  g_pooled[NG*JK];
__device__ float  g_cnt[NG];
__device__ float  g_dense[NG*DD];

// ---------------- preprocessing ----------------
__global__ void k_init() {
    int i = blockIdx.x*256 + threadIdx.x;
    if (i < NN) g_deg[i] = 0;
    if (i < NG*JK) g_pooled[i] = 0.0f;
    if (i < NG) g_cnt[i] = 0.0f;
}

__global__ void k_deg(const int* __restrict__ ei) {
    int e = blockIdx.x*256 + threadIdx.x;
    if (e < NE) atomicAdd(&g_deg[ei[NE + e]], 1);
}

__global__ void k_dinv_cnt(const int* __restrict__ batch) {
    int i = blockIdx.x*256 + threadIdx.x;
    if (i < NN) {
        g_dinv[i] = rsqrtf((float)g_deg[i] + 1.0f);   // +1 self loop
        atomicAdd(&g_cnt[batch[i]], 1.0f);
    }
}

// block-level inclusive scan (1024 elems/block)
__global__ __launch_bounds__(1024) void k_scan1() {
    __shared__ int sh[1024];
    int t = threadIdx.x;
    int i = blockIdx.x*1024 + t;
    int v = (i < NN) ? g_deg[i] : 0;
    sh[t] = v;
    __syncthreads();
    for (int off = 1; off < 1024; off <<= 1) {
        int add = (t >= off) ? sh[t - off] : 0;
        __syncthreads();
        sh[t] += add;
        __syncthreads();
    }
    if (i < NN) g_inc[i] = sh[t];
    if (t == 1023) g_part[blockIdx.x] = sh[1023];
}

__global__ void k_scan2() {
    if (threadIdx.x == 0) {
        int run = 0;
        for (int b = 0; b < NB_SCAN; b++) {
            int v = g_part[b];
            g_part[b] = run;
            run += v;
        }
    }
}

__global__ void k_scan3() {
    int i = blockIdx.x*256 + threadIdx.x;
    if (i < NN) {
        int off = g_inc[i] - g_deg[i] + g_part[i >> 10];
        g_off[i] = off;
        g_fill[i] = off;
    }
    if (i == 0) g_off[NN] = NE;
}

__global__ void k_reorder(const int* __restrict__ ei) {
    int e = blockIdx.x*256 + threadIdx.x;
    if (e < NE) {
        int s = ei[e];
        int d = ei[NE + e];
        int pos = atomicAdd(&g_fill[d], 1);
        float2 m;
        m.x = __int_as_float(s);
        m.y = g_dinv[s] * g_dinv[d];
        g_meta[pos] = m;
    }
}

// ---------------- tf32 tensor-core GEMM: g_bufA = X @ W ----------------
__device__ __forceinline__ unsigned f2tf32(float f) {
    unsigned u;
    asm("cvt.rna.tf32.f32 %0, %1;" : "=r"(u) : "f"(f));
    return u;
}

__global__ __launch_bounds__(256, 1) void k_gemm_tc(const float* __restrict__ Xext,
                                                    const float* __restrict__ W,
                                                    int use_ext) {
    const float* X = use_ext ? Xext : g_bufB;
    extern __shared__ unsigned sh[];
    unsigned* Xs = sh;                      // 128 x XS_STRIDE
    unsigned* Ws = sh + 128*XS_STRIDE;      // 128 x WS_STRIDE

    int t = threadIdx.x;
    int row0 = blockIdx.x * 128;

    // load W [k=128][n=128], tf32-rounded, padded stride
    for (int i = t; i < 128*32; i += 256) {
        int r = i >> 5, c4 = (i & 31) * 4;
        float4 v = *(const float4*)(W + r*128 + c4);
        unsigned* p = Ws + r*WS_STRIDE + c4;
        p[0] = f2tf32(v.x); p[1] = f2tf32(v.y); p[2] = f2tf32(v.z); p[3] = f2tf32(v.w);
    }
    // load X tile [128 rows][128 cols]
    for (int i = t; i < 128*32; i += 256) {
        int r = i >> 5, c4 = (i & 31) * 4;
        int row = row0 + r;
        float4 v = make_float4(0.f, 0.f, 0.f, 0.f);
        if (row < NN) v = *(const float4*)(X + (size_t)row*DD + c4);
        unsigned* p = Xs + r*XS_STRIDE + c4;
        p[0] = f2tf32(v.x); p[1] = f2tf32(v.y); p[2] = f2tf32(v.z); p[3] = f2tf32(v.w);
    }
    __syncthreads();

    int w = t >> 5, lane = t & 31;
    int gid = lane >> 2, tig = lane & 3;
    int rw = (w & 3) * 32;     // warp row base within tile
    int cw = (w >> 2) * 64;    // warp col base within tile

    float c[2][8][4];
    #pragma unroll
    for (int rt = 0; rt < 2; rt++)
        #pragma unroll
        for (int ct = 0; ct < 8; ct++)
            c[rt][ct][0] = c[rt][ct][1] = c[rt][ct][2] = c[rt][ct][3] = 0.f;

    #pragma unroll
    for (int ks = 0; ks < 16; ks++) {
        int k0 = ks * 8;
        unsigned a[2][4], b[8][2];
        #pragma unroll
        for (int rt = 0; rt < 2; rt++) {
            int rbase = rw + rt*16;
            a[rt][0] = Xs[(rbase + gid    )*XS_STRIDE + k0 + tig];
            a[rt][1] = Xs[(rbase + gid + 8)*XS_STRIDE + k0 + tig];
            a[rt][2] = Xs[(rbase + gid    )*XS_STRIDE + k0 + tig + 4];
            a[rt][3] = Xs[(rbase + gid + 8)*XS_STRIDE + k0 + tig + 4];
        }
        #pragma unroll
        for (int ct = 0; ct < 8; ct++) {
            int col = cw + ct*8 + gid;
            b[ct][0] = Ws[(k0 + tig    )*WS_STRIDE + col];
            b[ct][1] = Ws[(k0 + tig + 4)*WS_STRIDE + col];
        }
        #pragma unroll
        for (int rt = 0; rt < 2; rt++)
            #pragma unroll
            for (int ct = 0; ct < 8; ct++) {
                asm volatile(
                    "mma.sync.aligned.m16n8k8.row.col.f32.tf32.tf32.f32 "
                    "{%0,%1,%2,%3}, {%4,%5,%6,%7}, {%8,%9}, {%0,%1,%2,%3};"
                    : "+f"(c[rt][ct][0]), "+f"(c[rt][ct][1]),
                      "+f"(c[rt][ct][2]), "+f"(c[rt][ct][3])
                    : "r"(a[rt][0]), "r"(a[rt][1]), "r"(a[rt][2]), "r"(a[rt][3]),
                      "r"(b[ct][0]), "r"(b[ct][1]));
            }
    }

    // store C
    #pragma unroll
    for (int rt = 0; rt < 2; rt++) {
        #pragma unroll
        for (int ct = 0; ct < 8; ct++) {
            int r1 = row0 + rw + rt*16 + gid;
            int col = cw + ct*8 + tig*2;
            if (r1 < NN)
                *(float2*)(g_bufA + (size_t)r1*DD + col) = make_float2(c[rt][ct][0], c[rt][ct][1]);
            int r2 = r1 + 8;
            if (r2 < NN)
                *(float2*)(g_bufA + (size_t)r2*DD + col) = make_float2(c[rt][ct][2], c[rt][ct][3]);
        }
    }
}

// ---------------- fused CSR gather + self-loop + bias + relu + pooling ----------------
__global__ __launch_bounds__(256) void k_gather(const float* __restrict__ bias,
                                                const int* __restrict__ batch,
                                                int off_l) {
    int n = blockIdx.x*8 + (threadIdx.x >> 5);
    if (n >= NN) return;
    int lane = threadIdx.x & 31;

    int e0 = g_off[n];
    int e1 = g_off[n + 1];
    float di = g_dinv[n];

    float4 sv = *(const float4*)(g_bufA + (size_t)n*DD + lane*4);
    float w = di * di;
    float4 acc = make_float4(w*sv.x, w*sv.y, w*sv.z, w*sv.w);

    int e = e0;
    for (; e + 2 <= e1; e += 2) {
        float2 m0 = g_meta[e];
        float2 m1 = g_meta[e + 1];
        int s0 = __float_as_int(m0.x);
        int s1 = __float_as_int(m1.x);
        float4 v0 = *(const float4*)(g_bufA + (size_t)s0*DD + lane*4);
        float4 v1 = *(const float4*)(g_bufA + (size_t)s1*DD + lane*4);
        acc.x = fmaf(m0.y, v0.x, acc.x); acc.y = fmaf(m0.y, v0.y, acc.y);
        acc.z = fmaf(m0.y, v0.z, acc.z); acc.w = fmaf(m0.y, v0.w, acc.w);
        acc.x = fmaf(m1.y, v1.x, acc.x); acc.y = fmaf(m1.y, v1.y, acc.y);
        acc.z = fmaf(m1.y, v1.z, acc.z); acc.w = fmaf(m1.y, v1.w, acc.w);
    }
    if (e < e1) {
        float2 m0 = g_meta[e];
        int s0 = __float_as_int(m0.x);
        float4 v0 = *(const float4*)(g_bufA + (size_t)s0*DD + lane*4);
        acc.x = fmaf(m0.y, v0.x, acc.x); acc.y = fmaf(m0.y, v0.y, acc.y);
        acc.z = fmaf(m0.y, v0.z, acc.z); acc.w = fmaf(m0.y, v0.w, acc.w);
    }

    float4 b4 = ((const float4*)bias)[lane];
    acc.x = fmaxf(acc.x + b4.x, 0.f);
    acc.y = fmaxf(acc.y + b4.y, 0.f);
    acc.z = fmaxf(acc.z + b4.z, 0.f);
    acc.w = fmaxf(acc.w + b4.w, 0.f);

    *(float4*)(g_bufB + (size_t)n*DD + lane*4) = acc;

    int g = batch[n];
    float* q = g_pooled + g*JK + off_l + lane*4;
    asm volatile("red.global.add.v4.f32 [%0], {%1,%2,%3,%4};"
                 :: "l"(q), "f"(acc.x), "f"(acc.y), "f"(acc.z), "f"(acc.w) : "memory");
}

// ---------------- head: mean-pool normalize + lin1 + relu ----------------
__global__ __launch_bounds__(128) void k_head1(const float* __restrict__ l1w,
                                               const float* __restrict__ l1b) {
    int g = blockIdx.x;
    int j = threadIdx.x;
    __shared__ float ps[JK];
    float inv = 1.f / fmaxf(g_cnt[g], 1.f);
    for (int k = j; k < JK; k += 128) ps[k] = g_pooled[g*JK + k] * inv;
    __syncthreads();
    float s = l1b[j];
    #pragma unroll 4
    for (int k = 0; k < JK; k++) s = fmaf(ps[k], l1w[k*DD + j], s);
    g_dense[g*DD + j] = fmaxf(s, 0.f);
}

// ---------------- head: lin2 + log_softmax ----------------
__global__ __launch_bounds__(64) void k_head2(const float* __restrict__ l2w,
                                              const float* __restrict__ l2b,
                                              float* __restrict__ out) {
    __shared__ float ws[DD*10];
    __shared__ float bs[10];
    int t = threadIdx.x;
    for (int i = t; i < DD*10; i += 64) ws[i] = l2w[i];
    if (t < 10) bs[t] = l2b[t];
    __syncthreads();
    if (t < NG) {
        float z[10];
        #pragma unroll
        for (int c = 0; c < 10; c++) z[c] = bs[c];
        for (int k = 0; k < DD; k++) {
            float gv = g_dense[t*DD + k];
            #pragma unroll
            for (int c = 0; c < 10; c++) z[c] = fmaf(gv, ws[k*10 + c], z[c]);
        }
        float m = z[0];
        #pragma unroll
        for (int c = 1; c < 10; c++) m = fmaxf(m, z[c]);
        float ssum = 0.f;
        #pragma unroll
        for (int c = 0; c < 10; c++) ssum += expf(z[c] - m);
        float ls = m + logf(ssum);
        #pragma unroll
        for (int c = 0; c < 10; c++) out[t*10 + c] = z[c] - ls;
    }
}

// ---------------- launch ----------------
extern "C" void kernel_launch(void* const* d_in, const int* in_sizes, int n_in,
                              void* d_out, int out_size) {
    const float* x     = (const float*)d_in[0];
    const int*   ei    = (const int*)  d_in[1];
    const int*   batch = (const int*)  d_in[2];
    const float* W1 = (const float*)d_in[4];  const float* b1 = (const float*)d_in[5];
    const float* W2 = (const float*)d_in[6];  const float* b2 = (const float*)d_in[7];
    const float* W3 = (const float*)d_in[8];  const float* b3 = (const float*)d_in[9];
    const float* l1w = (const float*)d_in[10]; const float* l1b = (const float*)d_in[11];
    const float* l2w = (const float*)d_in[12]; const float* l2b = (const float*)d_in[13];
    float* out = (float*)d_out;

    static int smem_set = 0;
    if (!smem_set) {
        cudaFuncSetAttribute(k_gemm_tc, cudaFuncAttributeMaxDynamicSharedMemorySize,
                             (128*XS_STRIDE + 128*WS_STRIDE) * 4);
        smem_set = 1;
    }

    // preprocessing: degree, dinv, CSR by dst, edge reorder
    k_init    <<<(NN + 255)/256, 256>>>();
    k_deg     <<<(NE + 255)/256, 256>>>(ei);
    k_dinv_cnt<<<(NN + 255)/256, 256>>>(batch);
    k_scan1   <<<NB_SCAN, 1024>>>();
    k_scan2   <<<1, 32>>>();
    k_scan3   <<<(NN + 255)/256, 256>>>();
    k_reorder <<<(NE + 255)/256, 256>>>(ei);

    const float* Wl[3] = {W1, W2, W3};
    const float* bl[3] = {b1, b2, b3};
    for (int l = 0; l < 3; l++) {
        k_gemm_tc<<<(NN + 127)/128, 256, (128*XS_STRIDE + 128*WS_STRIDE)*4>>>(x, Wl[l], l == 0 ? 1 : 0);
        k_gather <<<(NN + 7)/8, 256>>>(bl[l], batch, l*DD);
    }

    k_head1<<<NG, 128>>>(l1w, l1b);
    k_head2<<<1, 64>>>(l2w, l2b, out);
}

// round 4
// speedup vs baseline: 2.0084x; 1.1670x over previous
#include <cuda_runtime.h>
#include <cuda_fp16.h>
#include <math.h>

#define NN 100000
#define NE 1600000
#define DD 128
#define NG 64
#define JK (3*DD)   // 384

#define NB_SCAN 98          // ceil(NN/1024)
#define XS_STRIDE 132
#define WS_STRIDE 136

// ---------------- scratch (device globals) ----------------
__device__ float  g_dinv[NN];
__device__ int    g_deg[NN];
__device__ int    g_inc[NN];
__device__ int    g_part[NB_SCAN];
__device__ int    g_off[NN + 1];
__device__ int    g_fill[NN];
__device__ float2 g_meta[NE];                 // {src bits, norm}, dst-sorted
__device__ __half g_half[(size_t)NN*DD];      // fp16 GEMM output (message buffer)
__device__ float  g_bufB[(size_t)NN*DD];      // layer output fp32
__device__ float  g_pooled[NG*JK];
__device__ float  g_cnt[NG];
__device__ float  g_dense[NG*DD];

// ---------------- preprocessing ----------------
__global__ void k_init() {
    int i = blockIdx.x*256 + threadIdx.x;
    if (i < NN) g_deg[i] = 0;
    if (i < NG*JK) g_pooled[i] = 0.0f;
    if (i < NG) g_cnt[i] = 0.0f;
}

__global__ void k_deg(const int* __restrict__ ei) {
    int e = blockIdx.x*256 + threadIdx.x;
    if (e < NE) atomicAdd(&g_deg[ei[NE + e]], 1);
}

__global__ void k_dinv_cnt(const int* __restrict__ batch) {
    int i = blockIdx.x*256 + threadIdx.x;
    if (i < NN) {
        g_dinv[i] = rsqrtf((float)g_deg[i] + 1.0f);
        atomicAdd(&g_cnt[batch[i]], 1.0f);
    }
}

__global__ __launch_bounds__(1024) void k_scan1() {
    __shared__ int sh[1024];
    int t = threadIdx.x;
    int i = blockIdx.x*1024 + t;
    int v = (i < NN) ? g_deg[i] : 0;
    sh[t] = v;
    __syncthreads();
    for (int off = 1; off < 1024; off <<= 1) {
        int add = (t >= off) ? sh[t - off] : 0;
        __syncthreads();
        sh[t] += add;
        __syncthreads();
    }
    if (i < NN) g_inc[i] = sh[t];
    if (t == 1023) g_part[blockIdx.x] = sh[1023];
}

__global__ void k_scan2() {
    if (threadIdx.x == 0) {
        int run = 0;
        for (int b = 0; b < NB_SCAN; b++) { int v = g_part[b]; g_part[b] = run; run += v; }
    }
}

__global__ void k_scan3() {
    int i = blockIdx.x*256 + threadIdx.x;
    if (i < NN) {
        int off = g_inc[i] - g_deg[i] + g_part[i >> 10];
        g_off[i] = off;
        g_fill[i] = off;
    }
    if (i == 0) g_off[NN] = NE;
}

__global__ void k_reorder(const int* __restrict__ ei) {
    int e = blockIdx.x*256 + threadIdx.x;
    if (e < NE) {
        int s = ei[e];
        int d = ei[NE + e];
        int pos = atomicAdd(&g_fill[d], 1);
        float2 m;
        m.x = __int_as_float(s);
        m.y = g_dinv[s] * g_dinv[d];
        g_meta[pos] = m;
    }
}

// ---------------- tf32 tensor-core GEMM: g_half = fp16(X @ W) ----------------
__device__ __forceinline__ unsigned f2tf32(float f) {
    unsigned u;
    asm("cvt.rna.tf32.f32 %0, %1;" : "=r"(u) : "f"(f));
    return u;
}

__global__ __launch_bounds__(256, 1) void k_gemm_tc(const float* __restrict__ Xext,
                                                    const float* __restrict__ W,
                                                    int use_ext) {
    const float* X = use_ext ? Xext : g_bufB;
    extern __shared__ unsigned sh[];
    unsigned* Xs = sh;
    unsigned* Ws = sh + 128*XS_STRIDE;

    int t = threadIdx.x;
    int row0 = blockIdx.x * 128;

    for (int i = t; i < 128*32; i += 256) {
        int r = i >> 5, c4 = (i & 31) * 4;
        float4 v = *(const float4*)(W + r*128 + c4);
        unsigned* p = Ws + r*WS_STRIDE + c4;
        p[0] = f2tf32(v.x); p[1] = f2tf32(v.y); p[2] = f2tf32(v.z); p[3] = f2tf32(v.w);
    }
    for (int i = t; i < 128*32; i += 256) {
        int r = i >> 5, c4 = (i & 31) * 4;
        int row = row0 + r;
        float4 v = make_float4(0.f, 0.f, 0.f, 0.f);
        if (row < NN) v = *(const float4*)(X + (size_t)row*DD + c4);
        unsigned* p = Xs + r*XS_STRIDE + c4;
        p[0] = f2tf32(v.x); p[1] = f2tf32(v.y); p[2] = f2tf32(v.z); p[3] = f2tf32(v.w);
    }
    __syncthreads();

    int w = t >> 5, lane = t & 31;
    int gid = lane >> 2, tig = lane & 3;
    int rw = (w & 3) * 32;
    int cw = (w >> 2) * 64;

    float c[2][8][4];
    #pragma unroll
    for (int rt = 0; rt < 2; rt++)
        #pragma unroll
        for (int ct = 0; ct < 8; ct++)
            c[rt][ct][0] = c[rt][ct][1] = c[rt][ct][2] = c[rt][ct][3] = 0.f;

    #pragma unroll
    for (int ks = 0; ks < 16; ks++) {
        int k0 = ks * 8;
        unsigned a[2][4], b[8][2];
        #pragma unroll
        for (int rt = 0; rt < 2; rt++) {
            int rbase = rw + rt*16;
            a[rt][0] = Xs[(rbase + gid    )*XS_STRIDE + k0 + tig];
            a[rt][1] = Xs[(rbase + gid + 8)*XS_STRIDE + k0 + tig];
            a[rt][2] = Xs[(rbase + gid    )*XS_STRIDE + k0 + tig + 4];
            a[rt][3] = Xs[(rbase + gid + 8)*XS_STRIDE + k0 + tig + 4];
        }
        #pragma unroll
        for (int ct = 0; ct < 8; ct++) {
            int col = cw + ct*8 + gid;
            b[ct][0] = Ws[(k0 + tig    )*WS_STRIDE + col];
            b[ct][1] = Ws[(k0 + tig + 4)*WS_STRIDE + col];
        }
        #pragma unroll
        for (int rt = 0; rt < 2; rt++)
            #pragma unroll
            for (int ct = 0; ct < 8; ct++) {
                asm volatile(
                    "mma.sync.aligned.m16n8k8.row.col.f32.tf32.tf32.f32 "
                    "{%0,%1,%2,%3}, {%4,%5,%6,%7}, {%8,%9}, {%0,%1,%2,%3};"
                    : "+f"(c[rt][ct][0]), "+f"(c[rt][ct][1]),
                      "+f"(c[rt][ct][2]), "+f"(c[rt][ct][3])
                    : "r"(a[rt][0]), "r"(a[rt][1]), "r"(a[rt][2]), "r"(a[rt][3]),
                      "r"(b[ct][0]), "r"(b[ct][1]));
            }
    }

    // store C as fp16
    #pragma unroll
    for (int rt = 0; rt < 2; rt++) {
        #pragma unroll
        for (int ct = 0; ct < 8; ct++) {
            int r1 = row0 + rw + rt*16 + gid;
            int col = cw + ct*8 + tig*2;
            if (r1 < NN)
                *(__half2*)(g_half + (size_t)r1*DD + col) = __floats2half2_rn(c[rt][ct][0], c[rt][ct][1]);
            int r2 = r1 + 8;
            if (r2 < NN)
                *(__half2*)(g_half + (size_t)r2*DD + col) = __floats2half2_rn(c[rt][ct][2], c[rt][ct][3]);
        }
    }
}

// ---------------- fused CSR gather (fp16 msgs) + self-loop + bias + relu + pooling ----------------
__device__ __forceinline__ float4 h4tof4(uint2 r) {
    __half2 a = *(__half2*)&r.x;
    __half2 b = *(__half2*)&r.y;
    float2 fa = __half22float2(a), fb = __half22float2(b);
    return make_float4(fa.x, fa.y, fb.x, fb.y);
}

__global__ __launch_bounds__(256) void k_gather(const float* __restrict__ bias,
                                                const int* __restrict__ batch,
                                                int off_l) {
    int n = blockIdx.x*8 + (threadIdx.x >> 5);
    if (n >= NN) return;
    int lane = threadIdx.x & 31;

    int e0 = g_off[n];
    int e1 = g_off[n + 1];
    float di = g_dinv[n];

    // self loop
    uint2 sraw = *(const uint2*)(g_half + (size_t)n*DD + lane*4);
    float4 sv = h4tof4(sraw);
    float w = di * di;
    float4 acc = make_float4(w*sv.x, w*sv.y, w*sv.z, w*sv.w);

    int e = e0;
    for (; e + 4 <= e1; e += 4) {
        float2 m0 = g_meta[e];
        float2 m1 = g_meta[e+1];
        float2 m2 = g_meta[e+2];
        float2 m3 = g_meta[e+3];
        uint2 r0 = *(const uint2*)(g_half + (size_t)__float_as_int(m0.x)*DD + lane*4);
        uint2 r1 = *(const uint2*)(g_half + (size_t)__float_as_int(m1.x)*DD + lane*4);
        uint2 r2 = *(const uint2*)(g_half + (size_t)__float_as_int(m2.x)*DD + lane*4);
        uint2 r3 = *(const uint2*)(g_half + (size_t)__float_as_int(m3.x)*DD + lane*4);
        float4 v0 = h4tof4(r0), v1 = h4tof4(r1), v2 = h4tof4(r2), v3 = h4tof4(r3);
        acc.x = fmaf(m0.y, v0.x, acc.x); acc.y = fmaf(m0.y, v0.y, acc.y);
        acc.z = fmaf(m0.y, v0.z, acc.z); acc.w = fmaf(m0.y, v0.w, acc.w);
        acc.x = fmaf(m1.y, v1.x, acc.x); acc.y = fmaf(m1.y, v1.y, acc.y);
        acc.z = fmaf(m1.y, v1.z, acc.z); acc.w = fmaf(m1.y, v1.w, acc.w);
        acc.x = fmaf(m2.y, v2.x, acc.x); acc.y = fmaf(m2.y, v2.y, acc.y);
        acc.z = fmaf(m2.y, v2.z, acc.z); acc.w = fmaf(m2.y, v2.w, acc.w);
        acc.x = fmaf(m3.y, v3.x, acc.x); acc.y = fmaf(m3.y, v3.y, acc.y);
        acc.z = fmaf(m3.y, v3.z, acc.z); acc.w = fmaf(m3.y, v3.w, acc.w);
    }
    for (; e < e1; e++) {
        float2 m0 = g_meta[e];
        uint2 r0 = *(const uint2*)(g_half + (size_t)__float_as_int(m0.x)*DD + lane*4);
        float4 v0 = h4tof4(r0);
        acc.x = fmaf(m0.y, v0.x, acc.x); acc.y = fmaf(m0.y, v0.y, acc.y);
        acc.z = fmaf(m0.y, v0.z, acc.z); acc.w = fmaf(m0.y, v0.w, acc.w);
    }

    float4 b4 = ((const float4*)bias)[lane];
    acc.x = fmaxf(acc.x + b4.x, 0.f);
    acc.y = fmaxf(acc.y + b4.y, 0.f);
    acc.z = fmaxf(acc.z + b4.z, 0.f);
    acc.w = fmaxf(acc.w + b4.w, 0.f);

    *(float4*)(g_bufB + (size_t)n*DD + lane*4) = acc;

    int g = batch[n];
    float* q = g_pooled + g*JK + off_l + lane*4;
    asm volatile("red.global.add.v4.f32 [%0], {%1,%2,%3,%4};"
                 :: "l"(q), "f"(acc.x), "f"(acc.y), "f"(acc.z), "f"(acc.w) : "memory");
}

// ---------------- head ----------------
__global__ __launch_bounds__(128) void k_head1(const float* __restrict__ l1w,
                                               const float* __restrict__ l1b) {
    int g = blockIdx.x;
    int j = threadIdx.x;
    __shared__ float ps[JK];
    float inv = 1.f / fmaxf(g_cnt[g], 1.f);
    for (int k = j; k < JK; k += 128) ps[k] = g_pooled[g*JK + k] * inv;
    __syncthreads();
    float s = l1b[j];
    #pragma unroll 4
    for (int k = 0; k < JK; k++) s = fmaf(ps[k], l1w[k*DD + j], s);
    g_dense[g*DD + j] = fmaxf(s, 0.f);
}

__global__ __launch_bounds__(64) void k_head2(const float* __restrict__ l2w,
                                              const float* __restrict__ l2b,
                                              float* __restrict__ out) {
    __shared__ float ws[DD*10];
    __shared__ float bs[10];
    int t = threadIdx.x;
    for (int i = t; i < DD*10; i += 64) ws[i] = l2w[i];
    if (t < 10) bs[t] = l2b[t];
    __syncthreads();
    if (t < NG) {
        float z[10];
        #pragma unroll
        for (int c = 0; c < 10; c++) z[c] = bs[c];
        for (int k = 0; k < DD; k++) {
            float gv = g_dense[t*DD + k];
            #pragma unroll
            for (int c = 0; c < 10; c++) z[c] = fmaf(gv, ws[k*10 + c], z[c]);
        }
        float m = z[0];
        #pragma unroll
        for (int c = 1; c < 10; c++) m = fmaxf(m, z[c]);
        float ssum = 0.f;
        #pragma unroll
        for (int c = 0; c < 10; c++) ssum += expf(z[c] - m);
        float ls = m + logf(ssum);
        #pragma unroll
        for (int c = 0; c < 10; c++) out[t*10 + c] = z[c] - ls;
    }
}

// ---------------- launch ----------------
extern "C" void kernel_launch(void* const* d_in, const int* in_sizes, int n_in,
                              void* d_out, int out_size) {
    const float* x     = (const float*)d_in[0];
    const int*   ei    = (const int*)  d_in[1];
    const int*   batch = (const int*)  d_in[2];
    const float* W1 = (const float*)d_in[4];  const float* b1 = (const float*)d_in[5];
    const float* W2 = (const float*)d_in[6];  const float* b2 = (const float*)d_in[7];
    const float* W3 = (const float*)d_in[8];  const float* b3 = (const float*)d_in[9];
    const float* l1w = (const float*)d_in[10]; const float* l1b = (const float*)d_in[11];
    const float* l2w = (const float*)d_in[12]; const float* l2b = (const float*)d_in[13];
    float* out = (float*)d_out;

    static int smem_set = 0;
    if (!smem_set) {
        cudaFuncSetAttribute(k_gemm_tc, cudaFuncAttributeMaxDynamicSharedMemorySize,
                             (128*XS_STRIDE + 128*WS_STRIDE) * 4);
        smem_set = 1;
    }

    k_init    <<<(NN + 255)/256, 256>>>();
    k_deg     <<<(NE + 255)/256, 256>>>(ei);
    k_dinv_cnt<<<(NN + 255)/256, 256>>>(batch);
    k_scan1   <<<NB_SCAN, 1024>>>();
    k_scan2   <<<1, 32>>>();
    k_scan3   <<<(NN + 255)/256, 256>>>();
    k_reorder <<<(NE + 255)/256, 256>>>(ei);

    const float* Wl[3] = {W1, W2, W3};
    const float* bl[3] = {b1, b2, b3};
    for (int l = 0; l < 3; l++) {
        k_gemm_tc<<<(NN + 127)/128, 256, (128*XS_STRIDE + 128*WS_STRIDE)*4>>>(x, Wl[l], l == 0 ? 1 : 0);
        k_gather <<<(NN + 7)/8, 256>>>(bl[l], batch, l*DD);
    }

    k_head1<<<NG, 128>>>(l1w, l1b);
    k_head2<<<1, 64>>>(l2w, l2b, out);
}